// round 7
// baseline (speedup 1.0000x reference)
#include <cuda_runtime.h>
#include <cstddef>
#include <cstdint>

// RoutingByAgreement: x[B,64,64] f32 -> v[B,64] f32, 3 iterations.
// 256-thread persistent CTAs (5/SM), double-buffered cp.async.
// No register copies of x: buf[k] stays valid for the whole batch body
// (the overwriting prefetch is issued only in the next loop iteration,
// after this iteration's final barrier).
// Layout B (s/squash):   t -> g=t>>6, d=t&63; column reads, bank = lane.
// Layout A (agreement):  t -> n=t>>2, q=t&3;  row LDS.128 + 16 FMA + 2 SHFL.

#define FULLMASK 0xffffffffu

static __device__ __forceinline__ void cp_async16(void* smem_dst, const void* gsrc) {
    uint32_t s = (uint32_t)__cvta_generic_to_shared(smem_dst);
    asm volatile("cp.async.cg.shared.global [%0], [%1], 16;\n" :: "r"(s), "l"(gsrc));
}
static __device__ __forceinline__ void cp_async_commit() {
    asm volatile("cp.async.commit_group;\n" ::: "memory");
}
template<int N> static __device__ __forceinline__ void cp_async_wait() {
    asm volatile("cp.async.wait_group %0;\n" :: "n"(N) : "memory");
}
static __device__ __forceinline__ float frcp(float x) {
    float r; asm("rcp.approx.f32 %0, %1;" : "=f"(r) : "f"(x)); return r;
}
static __device__ __forceinline__ float frsq(float x) {
    float r; asm("rsqrt.approx.f32 %0, %1;" : "=f"(r) : "f"(x)); return r;
}

__global__ void __launch_bounds__(256, 5)
routing_kernel(const float* __restrict__ x, float* __restrict__ out, int B)
{
    __shared__ __align__(16) float buf[2][4096];  // 32 KB double buffer [64][64]
    __shared__ __align__(16) float spart[4 * 64]; // per-group partial s
    __shared__ __align__(16) float sv[64];        // squashed v
    __shared__ __align__(16) float se[64];        // exp(logits), unnormalized

    const int t = threadIdx.x;
    const int l = t & 31;
    const int g = t >> 6, d = t & 63;  // layout B
    const int n = t >> 2, q = t & 3;   // layout A
    const int stride = gridDim.x;

    // prologue: prefetch first batch into buf[0]
    const int b0 = blockIdx.x;
    {
        const float* src = x + (size_t)b0 * 4096 + t * 16;
        float* dst = &buf[0][t * 16];
#pragma unroll
        for (int i = 0; i < 4; i++) cp_async16(dst + 4 * i, src + 4 * i);
    }
    cp_async_commit();

    int k = 0;
    for (int b = b0; b < B; b += stride, k ^= 1) {
        const int bn = b + stride;
        if (bn < B) {
            const float* src = x + (size_t)bn * 4096 + t * 16;
            float* dst = &buf[k ^ 1][t * 16];
#pragma unroll
            for (int i = 0; i < 4; i++) cp_async16(dst + 4 * i, src + 4 * i);
        }
        cp_async_commit();
        cp_async_wait<1>();            // current batch's group retired
        __syncthreads();               // buf[k] visible CTA-wide

        const float* __restrict__ bp = &buf[k][0];
        const float* __restrict__ colp = bp + d;        // column base (bank = lane)
        const float4* __restrict__ rowp =
            reinterpret_cast<const float4*>(bp + n * 64 + q * 16);

        float blog = 0.0f;             // logit register (valid in q==0 lanes)
        float v = 0.0f;

#pragma unroll
        for (int it = 0; it < 3; it++) {
            // ---- s-phase: p = sum_j w_j * x[16g+j][d] (unnormalized) ----
            float p, zinv;
            if (it == 0) {
                float p0 = 0.f, p1 = 0.f;
#pragma unroll
                for (int j = 0; j < 16; j += 2) {
                    p0 += colp[(16 * g + j) * 64];
                    p1 += colp[(16 * g + j + 1) * 64];
                }
                p = p0 + p1;
                zinv = 1.0f / 64.0f;   // softmax(0) = 1/64
            } else {
                float zl = se[l] + se[l + 32];
#pragma unroll
                for (int off = 16; off > 0; off >>= 1)
                    zl += __shfl_xor_sync(FULLMASK, zl, off);
                zinv = frcp(zl);
                float q0 = 0.f, q1 = 0.f;
                const float4* e4 = reinterpret_cast<const float4*>(&se[g * 16]);
#pragma unroll
                for (int m = 0; m < 4; m++) {
                    float4 e = e4[m];  // broadcast LDS.128
                    q0 += e.x * colp[(16 * g + 4 * m) * 64]
                        + e.y * colp[(16 * g + 4 * m + 1) * 64];
                    q1 += e.z * colp[(16 * g + 4 * m + 2) * 64]
                        + e.w * colp[(16 * g + 4 * m + 3) * 64];
                }
                p = q0 + q1;
            }
            spart[g * 64 + d] = p;
            __syncthreads();           // barrier A

            // ---- squash: pairs {d, d^32} across the warp cover all 64 ----
            const int dx = d ^ 32;
            float s0 = (spart[d]  + spart[64 + d]  + spart[128 + d]  + spart[192 + d])  * zinv;
            float s1 = (spart[dx] + spart[64 + dx] + spart[128 + dx] + spart[192 + dx]) * zinv;
            float nq = s0 * s0 + s1 * s1;
#pragma unroll
            for (int off = 16; off > 0; off >>= 1)
                nq += __shfl_xor_sync(FULLMASK, nq, off);
            float rn    = frsq(nq + 1e-20f);
            float nrm   = nq * rn;                          // sqrt(nq)
            float scale = nq * frcp((1.0f + nq) * (nrm + 1e-8f));
            v = s0 * scale;            // v for this thread's own d
            if (it == 2) break;        // uniform exit; final v held by g==0

            if (g == 0) sv[d] = v;     // broadcast v
            __syncthreads();           // barrier B

            // ---- agreement (layout A): a_n = <x[n], v> ----
            float a = 0.0f;
#pragma unroll
            for (int i = 0; i < 4; i++) {
                float4 xa = rowp[i];                        // row slice of x
                float4 va = *reinterpret_cast<const float4*>(&sv[q * 16 + 4 * i]);
                a += xa.x * va.x + xa.y * va.y + xa.z * va.z + xa.w * va.w;
            }
            a += __shfl_xor_sync(FULLMASK, a, 1);
            a += __shfl_xor_sync(FULLMASK, a, 2);
            if (q == 0) {              // owner lane for row n
                blog += a;
                se[n] = __expf(blog);  // |blog| small: shift-free softmax safe
            }
            __syncthreads();           // barrier C (se ready; spart WAR safe)
        }

        if (t < 64) out[(size_t)b * 64 + t] = v;   // g==0 covers all d
    }
}

extern "C" void kernel_launch(void* const* d_in, const int* in_sizes, int n_in,
                              void* d_out, int out_size)
{
    const float* x = (const float*)d_in[0];
    float* out = (float*)d_out;
    const int B = in_sizes[0] / 4096;
    int grid = 148 * 5;                // persistent: 5 CTAs per SM
    if (grid > B) grid = B;
    routing_kernel<<<grid, 256>>>(x, out, B);
}

// round 8
// speedup vs baseline: 1.0970x; 1.0970x over previous
#include <cuda_runtime.h>
#include <cstddef>
#include <cstdint>

// RoutingByAgreement: x[B,64,64] f32 -> v[B,64] f32, 3 iterations.
// 256-thread persistent CTAs (5/SM), double-buffered cp.async, approx FP.
// s-phase:  layout B registers xB[j] = x[16g+j][d]   (g=t>>6, d=t&63)
// agreement: layout A rows from smem buf (n=t>>2, q=t&3): 4xLDS.128 + 16 FMA
//            + 2 SHFL; owner lane q==0 keeps the logit in a register.
// buf[k] stays valid through the whole batch body (overwrite prefetch is
// issued only in the next loop iteration, after barrier C).

#define FULLMASK 0xffffffffu

static __device__ __forceinline__ void cp_async16(void* smem_dst, const void* gsrc) {
    uint32_t s = (uint32_t)__cvta_generic_to_shared(smem_dst);
    asm volatile("cp.async.cg.shared.global [%0], [%1], 16;\n" :: "r"(s), "l"(gsrc));
}
static __device__ __forceinline__ void cp_async_commit() {
    asm volatile("cp.async.commit_group;\n" ::: "memory");
}
template<int N> static __device__ __forceinline__ void cp_async_wait() {
    asm volatile("cp.async.wait_group %0;\n" :: "n"(N) : "memory");
}
static __device__ __forceinline__ float frcp(float x) {
    float r; asm("rcp.approx.f32 %0, %1;" : "=f"(r) : "f"(x)); return r;
}
static __device__ __forceinline__ float frsq(float x) {
    float r; asm("rsqrt.approx.f32 %0, %1;" : "=f"(r) : "f"(x)); return r;
}

__global__ void __launch_bounds__(256, 5)
routing_kernel(const float* __restrict__ x, float* __restrict__ out, int B)
{
    __shared__ __align__(16) float buf[2][4096];  // 32 KB double buffer [64][64]
    __shared__ __align__(16) float spart[4 * 64]; // per-group partial s
    __shared__ __align__(16) float sv[64];        // squashed v
    __shared__ __align__(16) float se[64];        // exp(logits), unnormalized

    const int t = threadIdx.x;
    const int l = t & 31;
    const int g = t >> 6, d = t & 63;  // layout B
    const int n = t >> 2, q = t & 3;   // layout A
    const int stride = gridDim.x;

    // prologue: prefetch first batch into buf[0]
    const int b0 = blockIdx.x;
    {
        const float* src = x + (size_t)b0 * 4096 + t * 16;
        float* dst = &buf[0][t * 16];
#pragma unroll
        for (int i = 0; i < 4; i++) cp_async16(dst + 4 * i, src + 4 * i);
    }
    cp_async_commit();

    int k = 0;
    for (int b = b0; b < B; b += stride, k ^= 1) {
        const int bn = b + stride;
        if (bn < B) {
            const float* src = x + (size_t)bn * 4096 + t * 16;
            float* dst = &buf[k ^ 1][t * 16];
#pragma unroll
            for (int i = 0; i < 4; i++) cp_async16(dst + 4 * i, src + 4 * i);
        }
        cp_async_commit();
        cp_async_wait<1>();            // current batch's group retired
        __syncthreads();               // buf[k] visible CTA-wide

        const float* __restrict__ bp = &buf[k][0];
        const float4* __restrict__ rowp =
            reinterpret_cast<const float4*>(bp + n * 64 + q * 16);

        // column slice into registers (bank = d mod 32 = lane: conflict-free)
        float xB[16];
#pragma unroll
        for (int j = 0; j < 16; j++) xB[j] = bp[(g * 16 + j) * 64 + d];

        float blog = 0.0f;             // logit register (valid in q==0 lanes)
        float v = 0.0f;

#pragma unroll
        for (int it = 0; it < 3; it++) {
            // ---- s-phase: p = sum_j w_j * xB_j (unnormalized weights) ----
            float p, zinv;
            if (it == 0) {
                float p0 = 0.f, p1 = 0.f;
#pragma unroll
                for (int j = 0; j < 16; j += 2) { p0 += xB[j]; p1 += xB[j + 1]; }
                p = p0 + p1;
                zinv = 1.0f / 64.0f;   // softmax(0) = 1/64
            } else {
                float zl = se[l] + se[l + 32];
#pragma unroll
                for (int off = 16; off > 0; off >>= 1)
                    zl += __shfl_xor_sync(FULLMASK, zl, off);
                zinv = frcp(zl);
                float q0 = 0.f, q1 = 0.f;
                const float4* e4 = reinterpret_cast<const float4*>(&se[g * 16]);
#pragma unroll
                for (int m = 0; m < 4; m++) {
                    float4 e = e4[m];  // broadcast LDS.128
                    q0 += e.x * xB[4 * m]     + e.y * xB[4 * m + 1];
                    q1 += e.z * xB[4 * m + 2] + e.w * xB[4 * m + 3];
                }
                p = q0 + q1;
            }
            spart[g * 64 + d] = p;
            __syncthreads();           // barrier A

            // ---- squash: pairs {d, d^32} across the warp cover all 64 ----
            const int dx = d ^ 32;
            float s0 = (spart[d]  + spart[64 + d]  + spart[128 + d]  + spart[192 + d])  * zinv;
            float s1 = (spart[dx] + spart[64 + dx] + spart[128 + dx] + spart[192 + dx]) * zinv;
            float nq = s0 * s0 + s1 * s1;
#pragma unroll
            for (int off = 16; off > 0; off >>= 1)
                nq += __shfl_xor_sync(FULLMASK, nq, off);
            float rn    = frsq(nq + 1e-20f);
            float nrm   = nq * rn;                          // sqrt(nq)
            float scale = nq * frcp((1.0f + nq) * (nrm + 1e-8f));
            v = s0 * scale;            // v for this thread's own d
            if (it == 2) break;        // uniform exit; final v held by g==0

            if (g == 0) sv[d] = v;     // broadcast v
            __syncthreads();           // barrier B

            // ---- agreement (layout A): a_n = <x[n], v> ----
            float a = 0.0f;
#pragma unroll
            for (int i = 0; i < 4; i++) {
                float4 xa = rowp[i];   // row slice from smem (buf[k] valid)
                float4 va = *reinterpret_cast<const float4*>(&sv[q * 16 + 4 * i]);
                a += xa.x * va.x + xa.y * va.y + xa.z * va.z + xa.w * va.w;
            }
            a += __shfl_xor_sync(FULLMASK, a, 1);
            a += __shfl_xor_sync(FULLMASK, a, 2);
            if (q == 0) {              // owner lane for row n
                blog += a;
                se[n] = __expf(blog);  // |blog| small: shift-free softmax safe
            }
            __syncthreads();           // barrier C (se ready; spart WAR safe)
        }

        if (t < 64) out[(size_t)b * 64 + t] = v;   // g==0 covers all d
    }
}

extern "C" void kernel_launch(void* const* d_in, const int* in_sizes, int n_in,
                              void* d_out, int out_size)
{
    const float* x = (const float*)d_in[0];
    float* out = (float*)d_out;
    const int B = in_sizes[0] / 4096;
    int grid = 148 * 5;                // persistent: 5 CTAs per SM
    if (grid > B) grid = B;
    routing_kernel<<<grid, 256>>>(x, out, B);
}

// round 9
// speedup vs baseline: 1.2550x; 1.1440x over previous
#include <cuda_runtime.h>
#include <cstddef>
#include <cstdint>

// RoutingByAgreement: x[B,64,64] f32 -> v[B,64] f32, 3 iterations.
// 256-thread persistent CTAs (4/SM), double-buffered cp.async, approx FP.
// s-phase:   layout B regs xB[j] = x[16g+j][d]        (g=t>>6, d=t&63)
// agreement: layout A regs xa[4] = x[n][16q..16q+16)  (n=t>>2, q=t&3)
//            16 FMA + 4 broadcast LDS.128 (sv) + 2 SHFL; owner lane q==0
//            keeps the logit in a register and writes exp directly.

#define FULLMASK 0xffffffffu

static __device__ __forceinline__ void cp_async16(void* smem_dst, const void* gsrc) {
    uint32_t s = (uint32_t)__cvta_generic_to_shared(smem_dst);
    asm volatile("cp.async.cg.shared.global [%0], [%1], 16;\n" :: "r"(s), "l"(gsrc));
}
static __device__ __forceinline__ void cp_async_commit() {
    asm volatile("cp.async.commit_group;\n" ::: "memory");
}
template<int N> static __device__ __forceinline__ void cp_async_wait() {
    asm volatile("cp.async.wait_group %0;\n" :: "n"(N) : "memory");
}
static __device__ __forceinline__ float frcp(float x) {
    float r; asm("rcp.approx.f32 %0, %1;" : "=f"(r) : "f"(x)); return r;
}
static __device__ __forceinline__ float frsq(float x) {
    float r; asm("rsqrt.approx.f32 %0, %1;" : "=f"(r) : "f"(x)); return r;
}

__global__ void __launch_bounds__(256, 4)
routing_kernel(const float* __restrict__ x, float* __restrict__ out, int B)
{
    __shared__ __align__(16) float buf[2][4096];  // 32 KB double buffer [64][64]
    __shared__ __align__(16) float spart[4 * 64]; // per-group partial s
    __shared__ __align__(16) float sv[64];        // squashed v
    __shared__ __align__(16) float se[64];        // exp(logits), unnormalized

    const int t = threadIdx.x;
    const int l = t & 31;
    const int g = t >> 6, d = t & 63;  // layout B
    const int n = t >> 2, q = t & 3;   // layout A
    const int stride = gridDim.x;

    // prologue: prefetch first batch into buf[0]
    const int b0 = blockIdx.x;
    {
        const float* src = x + (size_t)b0 * 4096 + t * 16;
        float* dst = &buf[0][t * 16];
#pragma unroll
        for (int i = 0; i < 4; i++) cp_async16(dst + 4 * i, src + 4 * i);
    }
    cp_async_commit();

    int k = 0;
    for (int b = b0; b < B; b += stride, k ^= 1) {
        const int bn = b + stride;
        if (bn < B) {
            const float* src = x + (size_t)bn * 4096 + t * 16;
            float* dst = &buf[k ^ 1][t * 16];
#pragma unroll
            for (int i = 0; i < 4; i++) cp_async16(dst + 4 * i, src + 4 * i);
        }
        cp_async_commit();
        cp_async_wait<1>();            // current batch's group retired
        __syncthreads();               // buf[k] visible CTA-wide

        const float* __restrict__ bp = &buf[k][0];

        // layout B column slice (16 scalar LDS, bank = lane: conflict-free)
        float xB[16];
#pragma unroll
        for (int j = 0; j < 16; j++) xB[j] = bp[(g * 16 + j) * 64 + d];

        // layout A row slice (4 LDS.128, once per batch)
        float4 xa[4];
        const float4* rowp = reinterpret_cast<const float4*>(bp + n * 64 + q * 16);
#pragma unroll
        for (int i = 0; i < 4; i++) xa[i] = rowp[i];

        float blog = 0.0f;             // logit register (valid in q==0 lanes)
        float v = 0.0f;

#pragma unroll
        for (int it = 0; it < 3; it++) {
            // ---- s-phase: p = sum_j w_j * xB_j (unnormalized weights) ----
            float p, zinv;
            if (it == 0) {
                float p0 = 0.f, p1 = 0.f;
#pragma unroll
                for (int j = 0; j < 16; j += 2) { p0 += xB[j]; p1 += xB[j + 1]; }
                p = p0 + p1;
                zinv = 1.0f / 64.0f;   // softmax(0) = 1/64
            } else {
                float zl = se[l] + se[l + 32];
#pragma unroll
                for (int off = 16; off > 0; off >>= 1)
                    zl += __shfl_xor_sync(FULLMASK, zl, off);
                zinv = frcp(zl);
                float q0 = 0.f, q1 = 0.f;
                const float4* e4 = reinterpret_cast<const float4*>(&se[g * 16]);
#pragma unroll
                for (int m = 0; m < 4; m++) {
                    float4 e = e4[m];  // broadcast LDS.128
                    q0 += e.x * xB[4 * m]     + e.y * xB[4 * m + 1];
                    q1 += e.z * xB[4 * m + 2] + e.w * xB[4 * m + 3];
                }
                p = q0 + q1;
            }
            spart[g * 64 + d] = p;
            __syncthreads();           // barrier A

            // ---- squash: pairs {d, d^32} across the warp cover all 64 ----
            const int dx = d ^ 32;
            float s0 = (spart[d]  + spart[64 + d]  + spart[128 + d]  + spart[192 + d])  * zinv;
            float s1 = (spart[dx] + spart[64 + dx] + spart[128 + dx] + spart[192 + dx]) * zinv;
            float nq = s0 * s0 + s1 * s1;
#pragma unroll
            for (int off = 16; off > 0; off >>= 1)
                nq += __shfl_xor_sync(FULLMASK, nq, off);
            float rn    = frsq(nq + 1e-20f);
            float nrm   = nq * rn;                          // sqrt(nq)
            float scale = nq * frcp((1.0f + nq) * (nrm + 1e-8f));
            v = s0 * scale;            // v for this thread's own d
            if (it == 2) break;        // uniform exit; final v held by g==0

            if (g == 0) sv[d] = v;     // broadcast v
            __syncthreads();           // barrier B

            // ---- agreement (layout A registers): a_n = <x[n], v> ----
            float a = 0.0f;
#pragma unroll
            for (int i = 0; i < 4; i++) {
                float4 va = *reinterpret_cast<const float4*>(&sv[q * 16 + 4 * i]);
                a += xa[i].x * va.x + xa[i].y * va.y
                   + xa[i].z * va.z + xa[i].w * va.w;
            }
            a += __shfl_xor_sync(FULLMASK, a, 1);
            a += __shfl_xor_sync(FULLMASK, a, 2);
            if (q == 0) {              // owner lane for row n
                blog += a;
                se[n] = __expf(blog);  // |blog| small: shift-free softmax safe
            }
            __syncthreads();           // barrier C (se ready; spart WAR safe)
        }

        if (t < 64) out[(size_t)b * 64 + t] = v;   // g==0 covers all d
    }
}

extern "C" void kernel_launch(void* const* d_in, const int* in_sizes, int n_in,
                              void* d_out, int out_size)
{
    const float* x = (const float*)d_in[0];
    float* out = (float*)d_out;
    const int B = in_sizes[0] / 4096;
    int grid = 148 * 4;                // persistent: 4 CTAs per SM
    if (grid > B) grid = B;
    routing_kernel<<<grid, 256>>>(x, out, B);
}